// round 8
// baseline (speedup 1.0000x reference)
#include <cuda_runtime.h>
#include <math.h>

// ---------------- compile-time forest constants ----------------
#define NTREES    32
#define MTREE     2047          // nodes per tree (2^11 - 1)
#define NNODES    (NTREES*MTREE)      // 65504
#define NINT_TREE 1023          // internal nodes per tree
#define NINTERNAL (NTREES*NINT_TREE)  // 32736
#define D 128

// ---------------- scratch (static device globals; no allocations) --------
__device__ float g_wx_iou[(size_t)NNODES * 384];   // ~100.6 MB
__device__ float g_wx_f [(size_t)NINTERNAL * D];   // ~16.8 MB
__device__ float g_c    [(size_t)NNODES * D];      // ~33.5 MB

__device__ __forceinline__ float sigf(float x) { return 1.0f / (1.0f + expf(-x)); }

// =========================================================================
// GEMM: Y[M,NC] = X'[M,128] @ W[128,NC] + b     (NC multiple of 64)
// REMAP: row m of the GEMM reads feature row (m/1023)*2047 + (m%1023)
// BM=BN=64, BK=64 (2 panels), 256 threads, 4x4 per-thread microtile.
// =========================================================================
template<bool REMAP>
__global__ void gemm128_kernel(const float* __restrict__ X,
                               const float* __restrict__ W,
                               const float* __restrict__ bias,
                               float* __restrict__ Y,
                               int M, int NC)
{
    __shared__ float As[64][68];   // padded stride 68 (conflict-free, float4-aligned)
    __shared__ float Bs[64][64];

    const int tid = threadIdx.x;
    const int tx = tid & 15, ty = tid >> 4;
    const int bm = blockIdx.x, bn = blockIdx.y;

    float acc[4][4];
#pragma unroll
    for (int i = 0; i < 4; ++i)
#pragma unroll
        for (int j = 0; j < 4; ++j) acc[i][j] = 0.0f;

    for (int kp = 0; kp < 2; ++kp) {
        // load A tile 64x64
#pragma unroll
        for (int i = 0; i < 4; ++i) {
            int r = (tid >> 4) + i * 16;     // 0..63
            int c = (tid & 15) * 4;
            int m = bm * 64 + r;
            float4 v = make_float4(0.f, 0.f, 0.f, 0.f);
            if (m < M) {
                int frow = m;
                if (REMAP) { int tr = m / NINT_TREE; frow = tr * MTREE + (m - tr * NINT_TREE); }
                v = *reinterpret_cast<const float4*>(X + (size_t)frow * 128 + kp * 64 + c);
            }
            *reinterpret_cast<float4*>(&As[r][c]) = v;
        }
        // load B tile 64x64
#pragma unroll
        for (int i = 0; i < 4; ++i) {
            int r = (tid >> 4) + i * 16;
            int c = (tid & 15) * 4;
            float4 v = *reinterpret_cast<const float4*>(W + (size_t)(kp * 64 + r) * NC + bn * 64 + c);
            *reinterpret_cast<float4*>(&Bs[r][c]) = v;
        }
        __syncthreads();

#pragma unroll 8
        for (int k = 0; k < 64; ++k) {
            float a0 = As[ty * 4 + 0][k];
            float a1 = As[ty * 4 + 1][k];
            float a2 = As[ty * 4 + 2][k];
            float a3 = As[ty * 4 + 3][k];
            float4 b = *reinterpret_cast<const float4*>(&Bs[k][tx * 4]);
            acc[0][0] += a0 * b.x; acc[0][1] += a0 * b.y; acc[0][2] += a0 * b.z; acc[0][3] += a0 * b.w;
            acc[1][0] += a1 * b.x; acc[1][1] += a1 * b.y; acc[1][2] += a1 * b.z; acc[1][3] += a1 * b.w;
            acc[2][0] += a2 * b.x; acc[2][1] += a2 * b.y; acc[2][2] += a2 * b.z; acc[2][3] += a2 * b.w;
            acc[3][0] += a3 * b.x; acc[3][1] += a3 * b.y; acc[3][2] += a3 * b.z; acc[3][3] += a3 * b.w;
        }
        __syncthreads();
    }

    float4 bv = *reinterpret_cast<const float4*>(bias + bn * 64 + tx * 4);
#pragma unroll
    for (int i = 0; i < 4; ++i) {
        int m = bm * 64 + ty * 4 + i;
        if (m < M) {
            float4 o;
            o.x = acc[i][0] + bv.x; o.y = acc[i][1] + bv.y;
            o.z = acc[i][2] + bv.z; o.w = acc[i][3] + bv.w;
            *reinterpret_cast<float4*>(Y + (size_t)m * NC + bn * 64 + tx * 4) = o;
        }
    }
}

// =========================================================================
// Leaf level (n=0): iou = wx_iou; c = i*u; h = o*tanh(c)
// =========================================================================
__global__ void leaf_kernel(float* __restrict__ h)
{
    int idx = blockIdx.x * blockDim.x + threadIdx.x;   // 32768*128 threads
    int nodeLocal = idx >> 7;          // 0..32767
    int k = idx & 127;
    int tree = nodeLocal >> 10;
    int r = nodeLocal & 1023;
    int g = tree * MTREE + 1023 + r;   // leaves are j in [1023,2047)
    size_t base = (size_t)g * 384;
    float i_ = sigf(g_wx_iou[base + k]);
    float o_ = sigf(g_wx_iou[base + 128 + k]);
    float u_ = tanhf(g_wx_iou[base + 256 + k]);
    float cn = i_ * u_;
    g_c[(size_t)g * D + k] = cn;
    h[(size_t)g * D + k]   = o_ * tanhf(cn);
}

// =========================================================================
// Internal level kernel (n = 10 - shift). Block = 16 parents, 256 threads.
// Per parent: 640 GEMM outputs (384 iou via h_sum, 128 f_l, 128 f_r),
// then fused activations + c/h update.
// Dynamic smem layout:
//   sHl[16*129], sHr[16*129], sHs[16*129], sU[128*64], sOut[16*640]
// =========================================================================
__global__ void level_kernel(const float* __restrict__ U_iou,
                             const float* __restrict__ U_f,
                             float* __restrict__ h,
                             int shift)
{
    extern __shared__ float sm[];
    float* sHl = sm;
    float* sHr = sHl + 16 * 129;
    float* sHs = sHr + 16 * 129;
    float* sU  = sHs + 16 * 129;        // 128 x 64 tile of U
    float* sOut = sU + 128 * 64;        // 16 x 640
    __shared__ int sG[16], sQ[16], sCLi[16], sCRi[16];

    const int tid = threadIdx.x;
    const int cnt = 1 << shift;

    if (tid < 16) {
        int p_idx = blockIdx.x * 16 + tid;   // P_tot always multiple of 16
        int tree = p_idx >> shift;
        int r = p_idx & (cnt - 1);
        int j = (cnt - 1) + r;               // first node at this depth is cnt-1
        sG[tid]   = tree * MTREE + j;
        sQ[tid]   = tree * NINT_TREE + j;
        sCLi[tid] = tree * MTREE + 2 * j + 1;
        sCRi[tid] = tree * MTREE + 2 * j + 2;
    }
    __syncthreads();

    // Phase A: load children h into smem, build h_sum
#pragma unroll
    for (int it = 0; it < 8; ++it) {
        int e = it * 256 + tid;
        int p = e >> 7, k = e & 127;
        float hl = h[(size_t)sCLi[p] * D + k];
        float hr = h[(size_t)sCRi[p] * D + k];
        sHl[p * 129 + k] = hl;
        sHr[p * 129 + k] = hr;
        sHs[p * 129 + k] = hl + hr;
    }
    __syncthreads();

    const int cg = tid & 15;   // column group (4 cols)
    const int p  = tid >> 4;   // parent row

    // Phase B: 8 column tiles of 64. Tiles 0..5: iou (A=Hs, B=U_iou).
    // Tiles 6,7: both f_l (A=Hl) and f_r (A=Hr) with B=U_f.
    for (int t = 0; t < 8; ++t) {
        const float* Usrc; int ldu, coff;
        if (t < 6) { Usrc = U_iou; ldu = 384; coff = t * 64; }
        else       { Usrc = U_f;   ldu = 128; coff = (t - 6) * 64; }
#pragma unroll
        for (int i = 0; i < 8; ++i) {
            int e = i * 256 + tid;        // 2048 float4 loads -> 128x64 tile
            int kr = e >> 4;
            int c4 = (e & 15) * 4;
            *reinterpret_cast<float4*>(&sU[kr * 64 + c4]) =
                *reinterpret_cast<const float4*>(Usrc + (size_t)kr * ldu + coff + c4);
        }
        __syncthreads();

        if (t < 6) {
            float ac0 = 0.f, ac1 = 0.f, ac2 = 0.f, ac3 = 0.f;
#pragma unroll 8
            for (int k = 0; k < 128; ++k) {
                float av = sHs[p * 129 + k];
                float4 b = *reinterpret_cast<const float4*>(&sU[k * 64 + cg * 4]);
                ac0 += av * b.x; ac1 += av * b.y; ac2 += av * b.z; ac3 += av * b.w;
            }
            int oc = t * 64 + cg * 4;
            sOut[p * 640 + oc + 0] = ac0;
            sOut[p * 640 + oc + 1] = ac1;
            sOut[p * 640 + oc + 2] = ac2;
            sOut[p * 640 + oc + 3] = ac3;
        } else {
            float l0 = 0.f, l1 = 0.f, l2 = 0.f, l3 = 0.f;
            float r0 = 0.f, r1 = 0.f, r2 = 0.f, r3 = 0.f;
#pragma unroll 8
            for (int k = 0; k < 128; ++k) {
                float al = sHl[p * 129 + k];
                float ar = sHr[p * 129 + k];
                float4 b = *reinterpret_cast<const float4*>(&sU[k * 64 + cg * 4]);
                l0 += al * b.x; l1 += al * b.y; l2 += al * b.z; l3 += al * b.w;
                r0 += ar * b.x; r1 += ar * b.y; r2 += ar * b.z; r3 += ar * b.w;
            }
            int oc = 384 + (t - 6) * 64 + cg * 4;
            sOut[p * 640 + oc + 0] = l0;
            sOut[p * 640 + oc + 1] = l1;
            sOut[p * 640 + oc + 2] = l2;
            sOut[p * 640 + oc + 3] = l3;
            sOut[p * 640 + 128 + oc + 0] = r0;
            sOut[p * 640 + 128 + oc + 1] = r1;
            sOut[p * 640 + 128 + oc + 2] = r2;
            sOut[p * 640 + 128 + oc + 3] = r3;
        }
        __syncthreads();
    }

    // Phase C: activations + c/h update
#pragma unroll
    for (int it = 0; it < 8; ++it) {
        int e = it * 256 + tid;
        int pp = e >> 7, k = e & 127;
        int g = sG[pp], q = sQ[pp], cl = sCLi[pp], cr = sCRi[pp];
        size_t wb = (size_t)g * 384;
        float wi = g_wx_iou[wb + k];
        float wo = g_wx_iou[wb + 128 + k];
        float wu = g_wx_iou[wb + 256 + k];
        float wf = g_wx_f[(size_t)q * 128 + k];
        const float* ob = &sOut[pp * 640];
        float i_ = sigf(ob[k]        + wi);
        float o_ = sigf(ob[128 + k]  + wo);
        float u_ = tanhf(ob[256 + k] + wu);
        float fl = sigf(ob[384 + k]  + wf);
        float fr = sigf(ob[512 + k]  + wf);
        float cL = g_c[(size_t)cl * D + k];
        float cR = g_c[(size_t)cr * D + k];
        float cn = i_ * u_ + fl * cL + fr * cR;
        g_c[(size_t)g * D + k] = cn;
        h[(size_t)g * D + k]   = o_ * tanhf(cn);
    }
}

// =========================================================================
// launch
// =========================================================================
extern "C" void kernel_launch(void* const* d_in, const int* in_sizes, int n_in,
                              void* d_out, int out_size)
{
    const float* features = (const float*)d_in[0];
    const float* W_iou    = (const float*)d_in[1];
    const float* b_iou    = (const float*)d_in[2];
    const float* U_iou    = (const float*)d_in[3];
    const float* W_f      = (const float*)d_in[4];
    const float* b_f      = (const float*)d_in[5];
    const float* U_f      = (const float*)d_in[6];
    float* h = (float*)d_out;
    (void)in_sizes; (void)n_in; (void)out_size;

    void* pa = nullptr; cudaGetSymbolAddress(&pa, g_wx_iou);
    void* pb = nullptr; cudaGetSymbolAddress(&pb, g_wx_f);
    float* wxiou = (float*)pa;
    float* wxf   = (float*)pb;

    // Precompute GEMMs
    gemm128_kernel<false><<<dim3((NNODES + 63) / 64, 384 / 64), 256>>>(
        features, W_iou, b_iou, wxiou, NNODES, 384);
    gemm128_kernel<true><<<dim3((NINTERNAL + 63) / 64, 128 / 64), 256>>>(
        features, W_f, b_f, wxf, NINTERNAL, 128);

    // Leaves
    leaf_kernel<<<(32768 * 128) / 256, 256>>>(h);

    // Internal levels, bottom-up
    const int smem_bytes = (3 * 16 * 129 + 128 * 64 + 16 * 640) * (int)sizeof(float);
    cudaFuncSetAttribute(level_kernel, cudaFuncAttributeMaxDynamicSharedMemorySize, smem_bytes);
    for (int n = 1; n <= 10; ++n) {
        int shift = 10 - n;                 // children-count exponent / depth
        int blocks = (32 << shift) / 16;    // P_tot / 16
        level_kernel<<<blocks, 256, smem_bytes>>>(U_iou, U_f, h, shift);
    }
}